// round 1
// baseline (speedup 1.0000x reference)
#include <cuda_runtime.h>
#include <cuda_bf16.h>

#define BB 8
#define NN 2048
#define BIGF 1e30f

// queries per thread / threads per block / ref tiling
#define QPT 2
#define TB  128
#define QCHUNK (QPT * TB)   // 256 queries per block
#define RTILE  128
#define RCHUNK 512

// Scratch (allocation-free rule): compacted valid points as float4 SoA-ish.
// g_valid[0] = clean (points+target), g_valid[1] = predp (points+pred)
__device__ float4       g_valid[2][BB][NN];
__device__ unsigned int g_minbits[2][BB][NN];  // per-query min distance bits
__device__ int          g_cnt[BB];
__device__ float        g_l1part[BB];

// ---------------------------------------------------------------------------
// Kernel 1: per-batch prep — l1 partial sum, compaction, padding, min init
// ---------------------------------------------------------------------------
__global__ void prep_kernel(const float* __restrict__ pred,
                            const float* __restrict__ target,
                            const int*   __restrict__ mask,
                            const float* __restrict__ points) {
    int b   = blockIdx.x;
    int tid = threadIdx.x;
    __shared__ int sh_cnt;
    if (tid == 0) sh_cnt = 0;
    __syncthreads();

    const unsigned int bigbits = __float_as_uint(BIGF);
    float l1acc = 0.f;

    for (int n = tid; n < NN; n += blockDim.x) {
        int gi = b * NN + n;
        const float* pp = pred   + gi * 3;
        const float* tt = target + gi * 3;
        const float* pt = points + gi * 3;
        float p0 = pp[0], p1 = pp[1], p2 = pp[2];
        float t0 = tt[0], t1 = tt[1], t2 = tt[2];
        float x0 = pt[0], x1 = pt[1], x2 = pt[2];
        int m = mask[gi];

        if (m) {
            l1acc += fabsf(p0 - t0) + fabsf(p1 - t1) + fabsf(p2 - t2);
            int k = atomicAdd(&sh_cnt, 1);   // order-independent compaction
            g_valid[0][b][k] = make_float4(x0 + t0, x1 + t1, x2 + t2, 0.f);
            g_valid[1][b][k] = make_float4(x0 + p0, x1 + p1, x2 + p2, 0.f);
        }
        g_minbits[0][b][n] = bigbits;
        g_minbits[1][b][n] = bigbits;
    }

    // block reduction of l1 partial
    __shared__ float red[256];
    red[tid] = l1acc;
    __syncthreads();
    for (int s = blockDim.x >> 1; s > 0; s >>= 1) {
        if (tid < s) red[tid] += red[tid + s];
        __syncthreads();
    }
    int cnt = sh_cnt;
    if (tid == 0) {
        g_l1part[b] = red[0];
        g_cnt[b]    = cnt;
    }

    // pad invalid tail with BIG so hot loop needs no per-element masking
    float4 bp = make_float4(BIGF, BIGF, BIGF, 0.f);
    for (int k = cnt + tid; k < NN; k += blockDim.x) {
        g_valid[0][b][k] = bp;
        g_valid[1][b][k] = bp;
    }
}

// ---------------------------------------------------------------------------
// Kernel 2: brute-force chamfer over compacted sets, both directions
// grid: (query chunks, ref chunks, 2*B tasks)
// ---------------------------------------------------------------------------
__global__ void chamfer_kernel() {
    int task = blockIdx.z;
    int b    = task >> 1;
    int dir  = task & 1;          // 0: clean->pred, 1: pred->clean
    int cnt  = g_cnt[b];

    int q_base = blockIdx.x * QCHUNK;
    if (q_base >= cnt) return;
    int cnt_r  = (cnt + RTILE - 1) & ~(RTILE - 1);  // padded entries are BIG
    int r_base = blockIdx.y * RCHUNK;
    if (r_base >= cnt_r) return;
    int r_end  = min(r_base + RCHUNK, cnt_r);

    int tid = threadIdx.x;
    const float4* __restrict__ Q = g_valid[dir][b];
    const float4* __restrict__ R = g_valid[dir ^ 1][b];

    float qx[QPT], qy[QPT], qz[QPT], mn[QPT];
#pragma unroll
    for (int u = 0; u < QPT; ++u) {
        int q = q_base + tid + u * TB;      // always < NN (in-bounds; BIG-padded)
        float4 v = Q[q];
        qx[u] = v.x; qy[u] = v.y; qz[u] = v.z;
        mn[u] = BIGF;
    }

    __shared__ float4 tile[RTILE];
    for (int r0 = r_base; r0 < r_end; r0 += RTILE) {
        tile[tid] = R[r0 + tid];            // TB == RTILE
        __syncthreads();
#pragma unroll 4
        for (int j = 0; j < RTILE; ++j) {
            float4 y = tile[j];             // uniform LDS.128 broadcast
#pragma unroll
            for (int u = 0; u < QPT; ++u) {
                float d = fabsf(qx[u] - y.x) + fabsf(qy[u] - y.y) + fabsf(qz[u] - y.z);
                mn[u] = fminf(mn[u], d);
            }
        }
        __syncthreads();
    }

#pragma unroll
    for (int u = 0; u < QPT; ++u) {
        int q = q_base + tid + u * TB;
        if (q < cnt)
            atomicMin(&g_minbits[dir][b][q], __float_as_uint(mn[u]));
    }
}

// ---------------------------------------------------------------------------
// Kernel 3: final scalar
// ---------------------------------------------------------------------------
__global__ void finalize_kernel(float* __restrict__ out) {
    int tid = threadIdx.x;
    float acc = 0.f;   // sum_b (S1[b]+S2[b]) / cnt[b]
    for (int b = 0; b < BB; ++b) {
        int cnt = g_cnt[b];
        float inv = 1.f / (float)cnt;
        float a = 0.f;
        for (int k = tid; k < cnt; k += blockDim.x) {
            a += __uint_as_float(g_minbits[0][b][k])
               + __uint_as_float(g_minbits[1][b][k]);
        }
        acc += a * inv;
    }
    __shared__ float red[512];
    red[tid] = acc;
    __syncthreads();
    for (int s = blockDim.x >> 1; s > 0; s >>= 1) {
        if (tid < s) red[tid] += red[tid + s];
        __syncthreads();
    }
    if (tid == 0) {
        float l1num = 0.f;
        int   msum  = 0;
        for (int b = 0; b < BB; ++b) { l1num += g_l1part[b]; msum += g_cnt[b]; }
        float l1 = l1num / 3.0f / (float)msum;
        float cd = red[0] / (float)BB;
        out[0] = l1 + expf(-l1) * cd;
    }
}

// ---------------------------------------------------------------------------
extern "C" void kernel_launch(void* const* d_in, const int* in_sizes, int n_in,
                              void* d_out, int out_size) {
    const float* pred   = (const float*)d_in[0];
    const float* target = (const float*)d_in[1];
    const int*   mask   = (const int*)  d_in[2];
    const float* points = (const float*)d_in[3];
    float* out = (float*)d_out;

    prep_kernel<<<BB, 256>>>(pred, target, mask, points);

    dim3 grid(NN / QCHUNK, (NN + RCHUNK - 1) / RCHUNK, 2 * BB);  // (8,4,16)
    chamfer_kernel<<<grid, TB>>>();

    finalize_kernel<<<1, 512>>>(out);
}

// round 2
// speedup vs baseline: 1.4637x; 1.4637x over previous
#include <cuda_runtime.h>
#include <cuda_bf16.h>

#define BB 8
#define NN 2048
#define BIGF 1e30f

// chamfer tiling
#define QPT 2
#define TB  128
#define QCHUNK (QPT * TB)   // 256 queries per block
#define RTILE  128          // one ref tile per block (max occupancy)

// Scratch (allocation-free rule).
// g_valid[0] = clean (points+target), g_valid[1] = predp (points+pred)
__device__ float4       g_valid[2][BB][NN];
__device__ unsigned int g_minbits[2][BB][NN];
__device__ int          g_cnt[BB];
__device__ float        g_l1part[BB * 8];   // one partial per prep block

// ---------------------------------------------------------------------------
// Kernel 1: prep — 64 blocks (8 slices x 8 batches), 1 point per thread.
// Compaction: shared counter -> one global atomicAdd per block for the base.
// ---------------------------------------------------------------------------
__global__ void prep_kernel(const float* __restrict__ pred,
                            const float* __restrict__ target,
                            const int*   __restrict__ mask,
                            const float* __restrict__ points) {
    int b   = blockIdx.x >> 3;         // batch
    int s   = blockIdx.x & 7;          // slice within batch
    int tid = threadIdx.x;             // 256 threads, 256 points per slice
    int n   = s * 256 + tid;
    int gi  = b * NN + n;

    const float* pp = pred   + gi * 3;
    const float* tt = target + gi * 3;
    const float* pt = points + gi * 3;
    float p0 = pp[0], p1 = pp[1], p2 = pp[2];
    float t0 = tt[0], t1 = tt[1], t2 = tt[2];
    float x0 = pt[0], x1 = pt[1], x2 = pt[2];
    int m = mask[gi];

    // init per-query min buffers
    const unsigned int bigbits = __float_as_uint(BIGF);
    g_minbits[0][b][n] = bigbits;
    g_minbits[1][b][n] = bigbits;

    float l1 = m ? (fabsf(p0 - t0) + fabsf(p1 - t1) + fabsf(p2 - t2)) : 0.f;

    // compaction: rank within block via shared atomic, block base via 1 global atomic
    __shared__ int sh_cnt, sh_base;
    if (tid == 0) sh_cnt = 0;
    __syncthreads();
    int k_local = -1;
    if (m) k_local = atomicAdd(&sh_cnt, 1);
    __syncthreads();
    if (tid == 0) sh_base = atomicAdd(&g_cnt[b], sh_cnt);

    // block reduction of l1 (warp shuffle + shared)
    __shared__ float wsum[8];
#pragma unroll
    for (int o = 16; o > 0; o >>= 1) l1 += __shfl_down_sync(0xffffffffu, l1, o);
    if ((tid & 31) == 0) wsum[tid >> 5] = l1;
    __syncthreads();
    if (tid < 8) {
        float v = wsum[tid];
#pragma unroll
        for (int o = 4; o > 0; o >>= 1) v += __shfl_down_sync(0xffu, v, o);
        if (tid == 0) g_l1part[blockIdx.x] = v;
    }

    if (m) {
        int k = sh_base + k_local;
        g_valid[0][b][k] = make_float4(x0 + t0, x1 + t1, x2 + t2, 0.f);
        g_valid[1][b][k] = make_float4(x0 + p0, x1 + p1, x2 + p2, 0.f);
    }
}

// ---------------------------------------------------------------------------
// Kernel 2: brute-force chamfer over compacted sets, both directions.
// grid: (q chunks, r tiles, 2*B). One 128-pt ref tile per block.
// ---------------------------------------------------------------------------
__global__ void chamfer_kernel() {
    int task = blockIdx.z;
    int b    = task >> 1;
    int dir  = task & 1;          // 0: clean->pred, 1: pred->clean
    int cnt  = g_cnt[b];

    int q_base = blockIdx.x * QCHUNK;
    if (q_base >= cnt) return;
    int r_base = blockIdx.y * RTILE;
    if (r_base >= cnt) return;

    int tid = threadIdx.x;
    const float4* __restrict__ Q = g_valid[dir][b];
    const float4* __restrict__ R = g_valid[dir ^ 1][b];

    __shared__ float4 tile[RTILE];
    {
        int r = r_base + tid;                    // TB == RTILE
        tile[tid] = (r < cnt) ? R[r] : make_float4(BIGF, BIGF, BIGF, 0.f);
    }

    float qx[QPT], qy[QPT], qz[QPT], mn[QPT];
#pragma unroll
    for (int u = 0; u < QPT; ++u) {
        int q = q_base + tid + u * TB;           // < NN; garbage beyond cnt is unused
        float4 v = Q[q];
        qx[u] = v.x; qy[u] = v.y; qz[u] = v.z;
        mn[u] = BIGF;
    }
    __syncthreads();

#pragma unroll 8
    for (int j = 0; j < RTILE; ++j) {
        float4 y = tile[j];                      // uniform LDS.128 broadcast
#pragma unroll
        for (int u = 0; u < QPT; ++u) {
            float d = fabsf(qx[u] - y.x) + fabsf(qy[u] - y.y) + fabsf(qz[u] - y.z);
            mn[u] = fminf(mn[u], d);
        }
    }

#pragma unroll
    for (int u = 0; u < QPT; ++u) {
        int q = q_base + tid + u * TB;
        if (q < cnt)
            atomicMin(&g_minbits[dir][b][q], __float_as_uint(mn[u]));
    }
}

// ---------------------------------------------------------------------------
// Kernel 3: final scalar
// ---------------------------------------------------------------------------
__global__ void finalize_kernel(float* __restrict__ out) {
    int tid = threadIdx.x;                      // 1024 threads
    float acc = 0.f;                            // sum_b (S1[b]+S2[b]) / cnt[b]
    for (int b = 0; b < BB; ++b) {
        int cnt = g_cnt[b];
        float inv = 1.f / (float)cnt;
        float a = 0.f;
        for (int k = tid; k < cnt; k += blockDim.x)
            a += __uint_as_float(g_minbits[0][b][k])
               + __uint_as_float(g_minbits[1][b][k]);
        acc += a * inv;
    }
    __shared__ float wsum[32];
#pragma unroll
    for (int o = 16; o > 0; o >>= 1) acc += __shfl_down_sync(0xffffffffu, acc, o);
    if ((tid & 31) == 0) wsum[tid >> 5] = acc;
    __syncthreads();
    if (tid < 32) {
        float v = wsum[tid];
#pragma unroll
        for (int o = 16; o > 0; o >>= 1) v += __shfl_down_sync(0xffffffffu, v, o);
        if (tid == 0) {
            float l1num = 0.f;
            int   msum  = 0;
#pragma unroll
            for (int i = 0; i < BB * 8; ++i) l1num += g_l1part[i];
#pragma unroll
            for (int b = 0; b < BB; ++b) msum += g_cnt[b];
            float l1 = l1num / 3.0f / (float)msum;
            float cd = v / (float)BB;
            out[0] = l1 + expf(-l1) * cd;
        }
    }
}

// ---------------------------------------------------------------------------
extern "C" void kernel_launch(void* const* d_in, const int* in_sizes, int n_in,
                              void* d_out, int out_size) {
    const float* pred   = (const float*)d_in[0];
    const float* target = (const float*)d_in[1];
    const int*   mask   = (const int*)  d_in[2];
    const float* points = (const float*)d_in[3];
    float* out = (float*)d_out;

    // reset per-batch counters (graph-capturable memset node; no allocation)
    void* cnt_ptr = nullptr;
    cudaGetSymbolAddress(&cnt_ptr, g_cnt);
    cudaMemsetAsync(cnt_ptr, 0, BB * sizeof(int));

    prep_kernel<<<BB * 8, 256>>>(pred, target, mask, points);

    dim3 grid(NN / QCHUNK, NN / RTILE, 2 * BB);   // (8, 16, 16); excess blocks exit
    chamfer_kernel<<<grid, TB>>>();

    finalize_kernel<<<1, 1024>>>(out);
}